// round 10
// baseline (speedup 1.0000x reference)
#include <cuda_runtime.h>
#include <cuda_fp16.h>
#include <math.h>
#include <stdint.h>

#define N_NODES 50000
#define N_EDGES 1600000
#define IN_F    512
#define NH      128
#define NC      40
#define SCAN_B  ((N_NODES + 255) / 256)   // 196 blocks
#define N_HALF  25000

// ---------------- static scratch (no runtime allocation) ----------------
__device__ int      g_deg_out_i[N_NODES];
__device__ int      g_deg_in_i [N_NODES];
__device__ int      g_cursor   [N_NODES];
__device__ int      g_row_ptr  [N_NODES + 1];
__device__ int      g_bsum     [256];
__device__ int      g_boff     [256];
__device__ int2     g_edge     [N_EDGES];           // (src, bits(ns[src])) grouped by dst
__device__ float    g_ns       [N_NODES];
__device__ float    g_nd       [N_NODES];
__device__ uint16_t g_w1t_hi   [NH * IN_F];         // W1^T bf16 hi, [n][k]
__device__ uint16_t g_w1t_lo   [NH * IN_F];         // W1^T bf16 lo, [n][k]
__device__ __half   g_h1       [(size_t)N_NODES * NH]; // X@W1 (unscaled, fp16)
__device__ float    g_x2       [(size_t)N_NODES * NH]; // relu(agg1*nd + b1)
__device__ __half   g_h2h      [(size_t)N_NODES * NC]; // x2@W2 (unscaled, fp16)

// ---------------- small helpers ----------------
__device__ __forceinline__ uint32_t smem_to_u32(const void* p) {
    uint32_t a;
    asm("{ .reg .u64 t; cvta.to.shared.u64 t, %1; cvt.u32.u64 %0, t; }" : "=r"(a) : "l"(p));
    return a;
}
__device__ __forceinline__ uint32_t packbf(float lo_elem, float hi_elem) {
    uint32_t r;
    asm("cvt.rn.bf16x2.f32 %0, %1, %2;" : "=r"(r) : "f"(hi_elem), "f"(lo_elem));
    return r;
}
__device__ __forceinline__ uint16_t bf16r(float x) {
    uint16_t r;
    asm("cvt.rn.bf16.f32 %0, %1;" : "=h"(r) : "f"(x));
    return r;
}
__device__ __forceinline__ void ldmx4(uint32_t* r, uint32_t addr) {
    asm volatile("ldmatrix.sync.aligned.m8n8.x4.shared.b16 {%0,%1,%2,%3}, [%4];"
                 : "=r"(r[0]), "=r"(r[1]), "=r"(r[2]), "=r"(r[3]) : "r"(addr));
}
__device__ __forceinline__ void mma_bf16(float* d, const uint32_t* a, const uint32_t* b) {
    asm volatile(
        "mma.sync.aligned.m16n8k16.row.col.f32.bf16.bf16.f32 "
        "{%0,%1,%2,%3}, {%4,%5,%6,%7}, {%8,%9}, {%0,%1,%2,%3};"
        : "+f"(d[0]), "+f"(d[1]), "+f"(d[2]), "+f"(d[3])
        : "r"(a[0]), "r"(a[1]), "r"(a[2]), "r"(a[3]), "r"(b[0]), "r"(b[1]));
}
__device__ __forceinline__ unsigned long long pack2(float x) {
    unsigned long long r;
    asm("mov.b64 %0, {%1, %1};" : "=l"(r) : "f"(x));
    return r;
}
__device__ __forceinline__ unsigned long long packf2(float lo, float hi) {
    unsigned long long r;
    asm("mov.b64 %0, {%1, %2};" : "=l"(r) : "f"(lo), "f"(hi));
    return r;
}
__device__ __forceinline__ void fma2(unsigned long long& d,
                                     unsigned long long a, unsigned long long b) {
    asm("fma.rn.f32x2 %0, %1, %2, %0;" : "+l"(d) : "l"(a), "l"(b));
}
__device__ __forceinline__ float2 unpack2(unsigned long long v) {
    float lo, hi;
    asm("mov.b64 {%0, %1}, %2;" : "=f"(lo), "=f"(hi) : "l"(v));
    return make_float2(lo, hi);
}

// ---------------- zero counters each call ----------------
__global__ void zero_kernel() {
    int i = blockIdx.x * blockDim.x + threadIdx.x;
    int stride = gridDim.x * blockDim.x;
    for (int j = i; j < N_NODES; j += stride) {
        g_deg_out_i[j] = 0;
        g_deg_in_i [j] = 0;
        g_cursor   [j] = 0;
    }
}

__global__ void deg_kernel(const int* __restrict__ src, const int* __restrict__ dst) {
    int e = blockIdx.x * blockDim.x + threadIdx.x;
    if (e < N_EDGES) {
        atomicAdd(&g_deg_out_i[src[e]], 1);
        atomicAdd(&g_deg_in_i [dst[e]], 1);
    }
}

__global__ void norm_kernel() {
    int i = blockIdx.x * blockDim.x + threadIdx.x;
    if (i < N_NODES) {
        g_ns[i] = rsqrtf(fmaxf((float)g_deg_out_i[i], 1.f));
        g_nd[i] = rsqrtf(fmaxf((float)g_deg_in_i [i], 1.f));
    }
}

// ---------------- hierarchical scan: deg_in -> row_ptr ----------------
__global__ __launch_bounds__(256) void scan1_kernel() {
    __shared__ int s[256];
    int i = blockIdx.x * 256 + threadIdx.x;
    s[threadIdx.x] = (i < N_NODES) ? g_deg_in_i[i] : 0;
    __syncthreads();
    for (int off = 128; off > 0; off >>= 1) {
        if (threadIdx.x < off) s[threadIdx.x] += s[threadIdx.x + off];
        __syncthreads();
    }
    if (threadIdx.x == 0) g_bsum[blockIdx.x] = s[0];
}

__global__ __launch_bounds__(256) void scan2_kernel() {
    __shared__ int s[256];
    int t = threadIdx.x;
    int v = (t < SCAN_B) ? g_bsum[t] : 0;
    s[t] = v;
    __syncthreads();
    for (int off = 1; off < 256; off <<= 1) {
        int u = (t >= off) ? s[t - off] : 0;
        __syncthreads();
        s[t] += u;
        __syncthreads();
    }
    g_boff[t] = s[t] - v;
    if (t == 255) g_row_ptr[N_NODES] = s[255];
}

__global__ __launch_bounds__(256) void scan3_kernel() {
    __shared__ int s[256];
    int t = threadIdx.x;
    int i = blockIdx.x * 256 + t;
    int v = (i < N_NODES) ? g_deg_in_i[i] : 0;
    s[t] = v;
    __syncthreads();
    for (int off = 1; off < 256; off <<= 1) {
        int u = (t >= off) ? s[t - off] : 0;
        __syncthreads();
        s[t] += u;
        __syncthreads();
    }
    if (i < N_NODES) g_row_ptr[i] = g_boff[blockIdx.x] + s[t] - v;
}

__global__ void fill_kernel(const int* __restrict__ src, const int* __restrict__ dst) {
    int e = blockIdx.x * blockDim.x + threadIdx.x;
    if (e < N_EDGES) {
        int d = dst[e];
        int s = src[e];
        int pos = g_row_ptr[d] + atomicAdd(&g_cursor[d], 1);
        g_edge[pos] = make_int2(s, __float_as_int(g_ns[s]));
    }
}

// ---------------- W1 -> transposed bf16 hi/lo split ----------------
__global__ void w1split_kernel(const float* __restrict__ W1) {
    int i = blockIdx.x * 256 + threadIdx.x;     // over 512*128
    if (i < IN_F * NH) {
        int k = i >> 7, n = i & 127;
        float w = W1[i];
        uint16_t hb = bf16r(w);
        float hf = __uint_as_float((uint32_t)hb << 16);
        uint16_t lb = bf16r(w - hf);
        g_w1t_hi[n * IN_F + k] = hb;
        g_w1t_lo[n * IN_F + k] = lb;
    }
}

// ---------------- GEMM1: h1 = X @ W1 via mma.sync bf16 3-term split --------
#define G1M_STAGE 32768
#define G1M_SMEM  (2 * G1M_STAGE)

__global__ __launch_bounds__(256) void gemm1_mma_kernel(const float* __restrict__ X) {
    extern __shared__ char smem[];
    const uint32_t sb = smem_to_u32(smem);
    const int tid  = threadIdx.x;
    const int lane = tid & 31;
    const int wid  = tid >> 5;
    const int bm   = blockIdx.x * 128;
    const int mw   = (wid & 3) * 32;     // warp M offset
    const int nw   = (wid >> 2) * 64;    // warp N offset

    float acc[2][8][4];
    #pragma unroll
    for (int i = 0; i < 2; i++)
        #pragma unroll
        for (int j = 0; j < 8; j++)
            #pragma unroll
            for (int q = 0; q < 4; q++) acc[i][j][q] = 0.f;

    const int lrow  = tid >> 1;
    const int lhalf = tid & 1;
    const int lsw   = (lrow >> 1) & 3;

    auto load_stage = [&](int st, int k0) {
        char* stg = smem + st * G1M_STAGE;
        {
            const int gr = bm + lrow;
            const bool ok = gr < N_NODES;
            const float* xp = &X[(size_t)gr * IN_F + k0 + lhalf * 16];
            #pragma unroll
            for (int q = 0; q < 4; q++) {
                float4 v = ok ? *reinterpret_cast<const float4*>(xp + q * 4)
                              : make_float4(0.f, 0.f, 0.f, 0.f);
                uint32_t h0 = packbf(v.x, v.y);
                uint32_t h1 = packbf(v.z, v.w);
                float l0 = v.x - __uint_as_float(h0 << 16);
                float l1 = v.y - __uint_as_float(h0 & 0xffff0000u);
                float l2 = v.z - __uint_as_float(h1 << 16);
                float l3 = v.w - __uint_as_float(h1 & 0xffff0000u);
                uint32_t p0 = packbf(l0, l1);
                uint32_t p1 = packbf(l2, l3);
                int c16 = lhalf * 2 + (q >> 1);
                uint32_t off = (uint32_t)(lrow * 64 + ((c16 ^ lsw) * 16) + (q & 1) * 8);
                *reinterpret_cast<uint2*>(stg + off)        = make_uint2(h0, h1);
                *reinterpret_cast<uint2*>(stg + 8192 + off) = make_uint2(p0, p1);
            }
        }
        {
            const uint16_t* bh = &g_w1t_hi[lrow * IN_F + k0 + lhalf * 16];
            const uint16_t* bl = &g_w1t_lo[lrow * IN_F + k0 + lhalf * 16];
            #pragma unroll
            for (int q = 0; q < 2; q++) {
                uint4 hv = *reinterpret_cast<const uint4*>(bh + q * 8);
                uint4 lv = *reinterpret_cast<const uint4*>(bl + q * 8);
                int c16 = lhalf * 2 + q;
                uint32_t off = (uint32_t)(lrow * 64 + ((c16 ^ lsw) * 16));
                *reinterpret_cast<uint4*>(stg + 16384 + off) = hv;
                *reinterpret_cast<uint4*>(stg + 24576 + off) = lv;
            }
        }
    };

    load_stage(0, 0);
    __syncthreads();

    const int a_rlane = lane & 15;
    const int a_kg    = lane >> 4;
    const int b_grp   = lane >> 3;
    const int b_rlane = (b_grp >> 1) * 8 + (lane & 7);
    const int b_kg    = b_grp & 1;

    const int NCHUNK = IN_F / 32;           // 16
    for (int c = 0; c < NCHUNK; c++) {
        const int cur = c & 1;
        if (c + 1 < NCHUNK) load_stage(cur ^ 1, (c + 1) * 32);

        const uint32_t sbase = sb + cur * G1M_STAGE;
        #pragma unroll
        for (int ks = 0; ks < 2; ks++) {
            uint32_t Ahi[2][4], Alo[2][4];
            #pragma unroll
            for (int mt = 0; mt < 2; mt++) {
                int row = mw + mt * 16 + a_rlane;
                uint32_t byteoff = (uint32_t)(row * 64 +
                    (((ks * 2 + a_kg) ^ ((row >> 1) & 3)) * 16));
                ldmx4(Ahi[mt], sbase + byteoff);
                ldmx4(Alo[mt], sbase + 8192 + byteoff);
            }
            uint32_t Bhi[8][2], Blo[8][2];
            #pragma unroll
            for (int ntp = 0; ntp < 4; ntp++) {
                int n = nw + ntp * 16 + b_rlane;
                uint32_t byteoff = (uint32_t)(n * 64 +
                    (((ks * 2 + b_kg) ^ ((n >> 1) & 3)) * 16));
                uint32_t rh[4], rl[4];
                ldmx4(rh, sbase + 16384 + byteoff);
                ldmx4(rl, sbase + 24576 + byteoff);
                Bhi[ntp * 2][0] = rh[0]; Bhi[ntp * 2][1] = rh[1];
                Bhi[ntp * 2 + 1][0] = rh[2]; Bhi[ntp * 2 + 1][1] = rh[3];
                Blo[ntp * 2][0] = rl[0]; Blo[ntp * 2][1] = rl[1];
                Blo[ntp * 2 + 1][0] = rl[2]; Blo[ntp * 2 + 1][1] = rl[3];
            }
            #pragma unroll
            for (int mt = 0; mt < 2; mt++)
                #pragma unroll
                for (int nt = 0; nt < 8; nt++)
                    mma_bf16(acc[mt][nt], Ahi[mt], Bhi[nt]);
            #pragma unroll
            for (int mt = 0; mt < 2; mt++)
                #pragma unroll
                for (int nt = 0; nt < 8; nt++)
                    mma_bf16(acc[mt][nt], Alo[mt], Bhi[nt]);
            #pragma unroll
            for (int mt = 0; mt < 2; mt++)
                #pragma unroll
                for (int nt = 0; nt < 8; nt++)
                    mma_bf16(acc[mt][nt], Ahi[mt], Blo[nt]);
        }
        __syncthreads();
    }

    // epilogue: convert to fp16 and store half2 per 2 cols
    #pragma unroll
    for (int mt = 0; mt < 2; mt++) {
        int row = bm + mw + mt * 16 + (lane >> 2);
        #pragma unroll
        for (int nt = 0; nt < 8; nt++) {
            int col = nw + nt * 8 + (lane & 3) * 2;
            __half2 p0 = __floats2half2_rn(acc[mt][nt][0], acc[mt][nt][1]);
            __half2 p1 = __floats2half2_rn(acc[mt][nt][2], acc[mt][nt][3]);
            if (row < N_NODES)
                *reinterpret_cast<__half2*>(&g_h1[(size_t)row * NH + col]) = p0;
            if (row + 8 < N_NODES)
                *reinterpret_cast<__half2*>(&g_h1[(size_t)(row + 8) * NH + col]) = p1;
        }
    }
}

// ---------------- agg1: paired-edge uint4 gather, fp32 accum ---------------
// lanes 0-15 handle even edge, 16-31 odd edge; combine via shfl_xor(16).
__global__ void agg1_kernel(const float* __restrict__ b1, int base, int count) {
    int t = blockIdx.x * blockDim.x + threadIdx.x;
    int w = (t >> 5);
    int lane = t & 31;
    if (w >= count) return;
    w += base;
    int beg = g_row_ptr[w], end = g_row_ptr[w + 1];

    const int half = lane >> 4;       // 0 / 1
    const int li   = lane & 15;       // 16B slot within 256B row

    unsigned long long a0 = 0ull, a1 = 0ull, a2 = 0ull, a3 = 0ull;
    for (int j = beg; j < end; j += 32) {
        int n = end - j; if (n > 32) n = 32;
        int2 ed = (j + lane < end) ? g_edge[j + lane] : make_int2(0, 0);
        #pragma unroll 8
        for (int i = 0; i < n; i += 2) {
            int e  = i + half;
            int   s = __shfl_sync(0xffffffffu, ed.x, e & 31);
            float f = __int_as_float(__shfl_sync(0xffffffffu, ed.y, e & 31));
            if (e >= n) { f = 0.f; s = 0; }
            uint4 v = __ldg(reinterpret_cast<const uint4*>(&g_h1[(size_t)s * NH]) + li);
            float2 f0 = __half22float2(*reinterpret_cast<__half2*>(&v.x));
            float2 f1 = __half22float2(*reinterpret_cast<__half2*>(&v.y));
            float2 f2 = __half22float2(*reinterpret_cast<__half2*>(&v.z));
            float2 f3 = __half22float2(*reinterpret_cast<__half2*>(&v.w));
            unsigned long long pf = pack2(f);
            fma2(a0, pf, packf2(f0.x, f0.y));
            fma2(a1, pf, packf2(f1.x, f1.y));
            fma2(a2, pf, packf2(f2.x, f2.y));
            fma2(a3, pf, packf2(f3.x, f3.y));
        }
    }
    // combine halves
    a0 += 0; // keep named
    unsigned long long c0 = __shfl_xor_sync(0xffffffffu, a0, 16);
    unsigned long long c1 = __shfl_xor_sync(0xffffffffu, a1, 16);
    unsigned long long c2 = __shfl_xor_sync(0xffffffffu, a2, 16);
    unsigned long long c3 = __shfl_xor_sync(0xffffffffu, a3, 16);
    float2 q0 = unpack2(a0), r0 = unpack2(c0);
    float2 q1 = unpack2(a1), r1 = unpack2(c1);
    float2 q2 = unpack2(a2), r2 = unpack2(c2);
    float2 q3 = unpack2(a3), r3 = unpack2(c3);

    if (half == 0) {
        float nd = g_nd[w];
        int fb = li * 8;
        float4 bA = __ldg(reinterpret_cast<const float4*>(b1 + fb));
        float4 bB = __ldg(reinterpret_cast<const float4*>(b1 + fb + 4));
        float4 oA, oB;
        oA.x = fmaxf((q0.x + r0.x) * nd + bA.x, 0.f);
        oA.y = fmaxf((q0.y + r0.y) * nd + bA.y, 0.f);
        oA.z = fmaxf((q1.x + r1.x) * nd + bA.z, 0.f);
        oA.w = fmaxf((q1.y + r1.y) * nd + bA.w, 0.f);
        oB.x = fmaxf((q2.x + r2.x) * nd + bB.x, 0.f);
        oB.y = fmaxf((q2.y + r2.y) * nd + bB.y, 0.f);
        oB.z = fmaxf((q3.x + r3.x) * nd + bB.z, 0.f);
        oB.w = fmaxf((q3.y + r3.y) * nd + bB.w, 0.f);
        *reinterpret_cast<float4*>(&g_x2[(size_t)w * NH + fb])     = oA;
        *reinterpret_cast<float4*>(&g_x2[(size_t)w * NH + fb + 4]) = oB;
    }
}

// ---------------- GEMM2 over [base, base+count): fp16 output ----------------
__global__ __launch_bounds__(256) void gemm2_kernel(const float* __restrict__ W2,
                                                    int base, int count) {
    __shared__ float W2s[NH * NC];
    __shared__ float xs[8][NH];

    int tid = threadIdx.x;
    for (int i = tid; i < NH * NC; i += 256) W2s[i] = W2[i];
    __syncthreads();

    const int n_tiles = (count + 7) / 8;
    for (int tile = blockIdx.x; tile < n_tiles; tile += gridDim.x) {
        int row0 = base + tile * 8;
        int lim  = base + count;
        #pragma unroll
        for (int i = 0; i < 4; i++) {
            int j = tid + i * 256;
            int r = j >> 7, k = j & 127;
            int row = row0 + r;
            xs[r][k] = (row < lim) ? g_x2[(size_t)row * NH + k] : 0.f;
        }
        __syncthreads();

        if (tid < 8 * (NC / 2)) {
            int r  = tid / (NC / 2);
            int cp = tid % (NC / 2);
            int row = row0 + r;
            if (row < lim) {
                unsigned long long acc = 0ull;
                const unsigned long long* wp =
                    reinterpret_cast<const unsigned long long*>(W2s) + cp;
                #pragma unroll 8
                for (int k = 0; k < NH; k++)
                    fma2(acc, pack2(xs[r][k]), wp[k * (NC / 2)]);
                float2 p = unpack2(acc);
                *reinterpret_cast<__half2*>(&g_h2h[(size_t)row * NC + cp * 2]) =
                    __floats2half2_rn(p.x, p.y);
            }
        }
        __syncthreads();
    }
}

// ---------------- agg2: fp16 gather; lanes 0-19 own 2 feats each -----------
__global__ void agg2_kernel(const float* __restrict__ b2, float* __restrict__ out) {
    int t = blockIdx.x * blockDim.x + threadIdx.x;
    int w = t >> 5, lane = t & 31;
    if (w >= N_NODES) return;
    int beg = g_row_ptr[w], end = g_row_ptr[w + 1];

    unsigned long long acc = 0ull;
    const bool act = lane < (NC / 2);
    for (int j = beg; j < end; j += 32) {
        int n = end - j; if (n > 32) n = 32;
        int2 ed = (j + lane < end) ? g_edge[j + lane] : make_int2(0, 0);
        #pragma unroll 8
        for (int i = 0; i < n; i++) {
            int   s = __shfl_sync(0xffffffffu, ed.x, i);
            float f = __int_as_float(__shfl_sync(0xffffffffu, ed.y, i));
            if (act) {
                uint32_t v = __ldg(reinterpret_cast<const uint32_t*>(
                    &g_h2h[(size_t)s * NC]) + lane);
                float2 fv = __half22float2(*reinterpret_cast<__half2*>(&v));
                fma2(acc, pack2(f), packf2(fv.x, fv.y));
            }
        }
    }
    if (act) {
        float nd = g_nd[w];
        float2 p = unpack2(acc);
        float2 bb = __ldg(reinterpret_cast<const float2*>(b2) + lane);
        *reinterpret_cast<float2*>(&out[(size_t)w * NC + lane * 2]) =
            make_float2(p.x * nd + bb.x, p.y * nd + bb.y);
    }
}

// ---------------- launch ----------------
extern "C" void kernel_launch(void* const* d_in, const int* in_sizes, int n_in,
                              void* d_out, int out_size) {
    const float* X   = (const float*)d_in[0];
    const float* W1  = (const float*)d_in[1];
    const float* b1  = (const float*)d_in[2];
    const float* W2  = (const float*)d_in[3];
    const float* b2  = (const float*)d_in[4];
    const int*   src = (const int*)  d_in[5];
    const int*   dst = (const int*)  d_in[6];
    float* out = (float*)d_out;

    static cudaStream_t s_side = nullptr;
    static cudaEvent_t  ev_fork = nullptr, ev_join = nullptr;
    static cudaEvent_t  ev_a = nullptr, ev_g2a = nullptr;
    if (s_side == nullptr) {
        cudaStreamCreateWithFlags(&s_side, cudaStreamNonBlocking);
        cudaEventCreateWithFlags(&ev_fork, cudaEventDisableTiming);
        cudaEventCreateWithFlags(&ev_join, cudaEventDisableTiming);
        cudaEventCreateWithFlags(&ev_a, cudaEventDisableTiming);
        cudaEventCreateWithFlags(&ev_g2a, cudaEventDisableTiming);
        cudaFuncSetAttribute(gemm1_mma_kernel,
                             cudaFuncAttributeMaxDynamicSharedMemorySize, G1M_SMEM);
    }

    // fork: side stream runs the graph-prep chain
    cudaEventRecord(ev_fork, 0);
    cudaStreamWaitEvent(s_side, ev_fork, 0);

    zero_kernel<<<256, 256, 0, s_side>>>();
    deg_kernel<<<(N_EDGES + 255) / 256, 256, 0, s_side>>>(src, dst);
    norm_kernel<<<(N_NODES + 255) / 256, 256, 0, s_side>>>();
    scan1_kernel<<<SCAN_B, 256, 0, s_side>>>();
    scan2_kernel<<<1, 256, 0, s_side>>>();
    scan3_kernel<<<SCAN_B, 256, 0, s_side>>>();
    fill_kernel<<<(N_EDGES + 255) / 256, 256, 0, s_side>>>(src, dst);

    // main stream: W1 split + tensor-core GEMM1
    w1split_kernel<<<(IN_F * NH + 255) / 256, 256>>>(W1);
    gemm1_mma_kernel<<<(N_NODES + 127) / 128, 256, G1M_SMEM>>>(X);

    // join
    cudaEventRecord(ev_join, s_side);
    cudaStreamWaitEvent(0, ev_join, 0);

    // agg1 half A; gemm2(A) overlaps agg1 half B
    agg1_kernel<<<(N_HALF * 32 + 255) / 256, 256>>>(b1, 0, N_HALF);
    cudaEventRecord(ev_a, 0);
    cudaStreamWaitEvent(s_side, ev_a, 0);
    gemm2_kernel<<<1024, 256, 0, s_side>>>(W2, 0, N_HALF);

    agg1_kernel<<<((N_NODES - N_HALF) * 32 + 255) / 256, 256>>>(b1, N_HALF, N_NODES - N_HALF);
    gemm2_kernel<<<1024, 256>>>(W2, N_HALF, N_NODES - N_HALF);

    cudaEventRecord(ev_g2a, s_side);
    cudaStreamWaitEvent(0, ev_g2a, 0);

    agg2_kernel<<<(N_NODES * 32 + 255) / 256, 256>>>(b2, out);
}

// round 12
// speedup vs baseline: 1.0982x; 1.0982x over previous
#include <cuda_runtime.h>
#include <cuda_fp16.h>
#include <math.h>
#include <stdint.h>

#define N_NODES 50000
#define N_EDGES 1600000
#define IN_F    512
#define NH      128
#define NC      40
#define SCAN_B  ((N_NODES + 255) / 256)   // 196 blocks
#define N_HALF  25000

// ---------------- static scratch (no runtime allocation) ----------------
__device__ int      g_deg_out_i[N_NODES];
__device__ int      g_deg_in_i [N_NODES];
__device__ int      g_cursor   [N_NODES];
__device__ int      g_row_ptr  [N_NODES + 1];
__device__ int      g_bsum     [256];
__device__ int      g_boff     [256];
__device__ int2     g_edge     [N_EDGES];           // (src, bits(ns[src])) grouped by dst
__device__ float    g_ns       [N_NODES];
__device__ float    g_nd       [N_NODES];
__device__ uint16_t g_w1t_hi   [NH * IN_F];         // W1^T fp16, [n][k]
__device__ __half   g_h1       [(size_t)N_NODES * NH]; // X@W1 (unscaled, fp16)
__device__ float    g_x2       [(size_t)N_NODES * NH]; // relu(agg1*nd + b1)
__device__ __half   g_h2h      [(size_t)N_NODES * NC]; // x2@W2 (unscaled, fp16)

// ---------------- small helpers ----------------
__device__ __forceinline__ uint32_t smem_to_u32(const void* p) {
    uint32_t a;
    asm("{ .reg .u64 t; cvta.to.shared.u64 t, %1; cvt.u32.u64 %0, t; }" : "=r"(a) : "l"(p));
    return a;
}
__device__ __forceinline__ void ldmx4(uint32_t* r, uint32_t addr) {
    asm volatile("ldmatrix.sync.aligned.m8n8.x4.shared.b16 {%0,%1,%2,%3}, [%4];"
                 : "=r"(r[0]), "=r"(r[1]), "=r"(r[2]), "=r"(r[3]) : "r"(addr));
}
__device__ __forceinline__ void mma_f16(float* d, const uint32_t* a, const uint32_t* b) {
    asm volatile(
        "mma.sync.aligned.m16n8k16.row.col.f32.f16.f16.f32 "
        "{%0,%1,%2,%3}, {%4,%5,%6,%7}, {%8,%9}, {%0,%1,%2,%3};"
        : "+f"(d[0]), "+f"(d[1]), "+f"(d[2]), "+f"(d[3])
        : "r"(a[0]), "r"(a[1]), "r"(a[2]), "r"(a[3]), "r"(b[0]), "r"(b[1]));
}
__device__ __forceinline__ unsigned long long pack2(float x) {
    unsigned long long r;
    asm("mov.b64 %0, {%1, %1};" : "=l"(r) : "f"(x));
    return r;
}
__device__ __forceinline__ unsigned long long packf2(float lo, float hi) {
    unsigned long long r;
    asm("mov.b64 %0, {%1, %2};" : "=l"(r) : "f"(lo), "f"(hi));
    return r;
}
__device__ __forceinline__ void fma2(unsigned long long& d,
                                     unsigned long long a, unsigned long long b) {
    asm("fma.rn.f32x2 %0, %1, %2, %0;" : "+l"(d) : "l"(a), "l"(b));
}
__device__ __forceinline__ float2 unpack2(unsigned long long v) {
    float lo, hi;
    asm("mov.b64 {%0, %1}, %2;" : "=f"(lo), "=f"(hi) : "l"(v));
    return make_float2(lo, hi);
}

// ---------------- zero counters each call ----------------
__global__ void zero_kernel() {
    int i = blockIdx.x * blockDim.x + threadIdx.x;
    int stride = gridDim.x * blockDim.x;
    for (int j = i; j < N_NODES; j += stride) {
        g_deg_out_i[j] = 0;
        g_deg_in_i [j] = 0;
        g_cursor   [j] = 0;
    }
}

__global__ void deg_kernel(const int* __restrict__ src, const int* __restrict__ dst) {
    int e = blockIdx.x * blockDim.x + threadIdx.x;
    if (e < N_EDGES) {
        atomicAdd(&g_deg_out_i[src[e]], 1);
        atomicAdd(&g_deg_in_i [dst[e]], 1);
    }
}

__global__ void norm_kernel() {
    int i = blockIdx.x * blockDim.x + threadIdx.x;
    if (i < N_NODES) {
        g_ns[i] = rsqrtf(fmaxf((float)g_deg_out_i[i], 1.f));
        g_nd[i] = rsqrtf(fmaxf((float)g_deg_in_i [i], 1.f));
    }
}

// ---------------- hierarchical scan: deg_in -> row_ptr ----------------
__global__ __launch_bounds__(256) void scan1_kernel() {
    __shared__ int s[256];
    int i = blockIdx.x * 256 + threadIdx.x;
    s[threadIdx.x] = (i < N_NODES) ? g_deg_in_i[i] : 0;
    __syncthreads();
    for (int off = 128; off > 0; off >>= 1) {
        if (threadIdx.x < off) s[threadIdx.x] += s[threadIdx.x + off];
        __syncthreads();
    }
    if (threadIdx.x == 0) g_bsum[blockIdx.x] = s[0];
}

__global__ __launch_bounds__(256) void scan2_kernel() {
    __shared__ int s[256];
    int t = threadIdx.x;
    int v = (t < SCAN_B) ? g_bsum[t] : 0;
    s[t] = v;
    __syncthreads();
    for (int off = 1; off < 256; off <<= 1) {
        int u = (t >= off) ? s[t - off] : 0;
        __syncthreads();
        s[t] += u;
        __syncthreads();
    }
    g_boff[t] = s[t] - v;
    if (t == 255) g_row_ptr[N_NODES] = s[255];
}

__global__ __launch_bounds__(256) void scan3_kernel() {
    __shared__ int s[256];
    int t = threadIdx.x;
    int i = blockIdx.x * 256 + t;
    int v = (i < N_NODES) ? g_deg_in_i[i] : 0;
    s[t] = v;
    __syncthreads();
    for (int off = 1; off < 256; off <<= 1) {
        int u = (t >= off) ? s[t - off] : 0;
        __syncthreads();
        s[t] += u;
        __syncthreads();
    }
    if (i < N_NODES) g_row_ptr[i] = g_boff[blockIdx.x] + s[t] - v;
}

__global__ void fill_kernel(const int* __restrict__ src, const int* __restrict__ dst) {
    int e = blockIdx.x * blockDim.x + threadIdx.x;
    if (e < N_EDGES) {
        int d = dst[e];
        int s = src[e];
        int pos = g_row_ptr[d] + atomicAdd(&g_cursor[d], 1);
        g_edge[pos] = make_int2(s, __float_as_int(g_ns[s]));
    }
}

// ---------------- W1 -> transposed fp16 ----------------
__global__ void w1split_kernel(const float* __restrict__ W1) {
    int i = blockIdx.x * 256 + threadIdx.x;     // over 512*128
    if (i < IN_F * NH) {
        int k = i >> 7, n = i & 127;
        __half h = __float2half_rn(W1[i]);
        g_w1t_hi[n * IN_F + k] = __half_as_ushort(h);
    }
}

// ---------------- GEMM1: h1 = X @ W1 via mma.sync fp16 2-term split --------
// CTA 128x128, 8 warps (4M x 2N), warp 32x64, K-chunk 32, 2 stages.
// smem stage (24KB): Ahi[128][32]f16 @0, Alo @8192, Bhi @16384.
#define G1M_STAGE 24576
#define G1M_SMEM  (2 * G1M_STAGE)

__global__ __launch_bounds__(256) void gemm1_mma_kernel(const float* __restrict__ X) {
    extern __shared__ char smem[];
    const uint32_t sb = smem_to_u32(smem);
    const int tid  = threadIdx.x;
    const int lane = tid & 31;
    const int wid  = tid >> 5;
    const int bm   = blockIdx.x * 128;
    const int mw   = (wid & 3) * 32;     // warp M offset
    const int nw   = (wid >> 2) * 64;    // warp N offset

    float acc[2][8][4];
    #pragma unroll
    for (int i = 0; i < 2; i++)
        #pragma unroll
        for (int j = 0; j < 8; j++)
            #pragma unroll
            for (int q = 0; q < 4; q++) acc[i][j][q] = 0.f;

    const int lrow  = tid >> 1;
    const int lhalf = tid & 1;
    const int lsw   = (lrow >> 1) & 3;

    auto load_stage = [&](int st, int k0) {
        char* stg = smem + st * G1M_STAGE;
        // A: X rows -> fp16 hi/lo
        {
            const int gr = bm + lrow;
            const bool ok = gr < N_NODES;
            const float* xp = &X[(size_t)gr * IN_F + k0 + lhalf * 16];
            #pragma unroll
            for (int q = 0; q < 4; q++) {
                float4 v = ok ? *reinterpret_cast<const float4*>(xp + q * 4)
                              : make_float4(0.f, 0.f, 0.f, 0.f);
                __half2 ha = __floats2half2_rn(v.x, v.y);
                __half2 hb = __floats2half2_rn(v.z, v.w);
                float2 haf = __half22float2(ha);
                float2 hbf = __half22float2(hb);
                __half2 la = __floats2half2_rn(v.x - haf.x, v.y - haf.y);
                __half2 lb = __floats2half2_rn(v.z - hbf.x, v.w - hbf.y);
                uint32_t hau, hbu, lau, lbu;
                memcpy(&hau, &ha, 4); memcpy(&hbu, &hb, 4);
                memcpy(&lau, &la, 4); memcpy(&lbu, &lb, 4);
                int c16 = lhalf * 2 + (q >> 1);
                uint32_t off = (uint32_t)(lrow * 64 + ((c16 ^ lsw) * 16) + (q & 1) * 8);
                *reinterpret_cast<uint2*>(stg + off)        = make_uint2(hau, hbu);
                *reinterpret_cast<uint2*>(stg + 8192 + off) = make_uint2(lau, lbu);
            }
        }
        // B: pre-converted W1^T fp16, copy 32-k slice
        {
            const uint16_t* bh = &g_w1t_hi[lrow * IN_F + k0 + lhalf * 16];
            #pragma unroll
            for (int q = 0; q < 2; q++) {
                uint4 hv = *reinterpret_cast<const uint4*>(bh + q * 8);
                int c16 = lhalf * 2 + q;
                uint32_t off = (uint32_t)(lrow * 64 + ((c16 ^ lsw) * 16));
                *reinterpret_cast<uint4*>(stg + 16384 + off) = hv;
            }
        }
    };

    load_stage(0, 0);
    __syncthreads();

    const int a_rlane = lane & 15;
    const int a_kg    = lane >> 4;
    const int b_grp   = lane >> 3;
    const int b_rlane = (b_grp >> 1) * 8 + (lane & 7);
    const int b_kg    = b_grp & 1;

    const int NCHUNK = IN_F / 32;           // 16
    for (int c = 0; c < NCHUNK; c++) {
        const int cur = c & 1;
        if (c + 1 < NCHUNK) load_stage(cur ^ 1, (c + 1) * 32);

        const uint32_t sbase = sb + cur * G1M_STAGE;
        #pragma unroll
        for (int ks = 0; ks < 2; ks++) {
            uint32_t Ahi[2][4], Alo[2][4];
            #pragma unroll
            for (int mt = 0; mt < 2; mt++) {
                int row = mw + mt * 16 + a_rlane;
                uint32_t byteoff = (uint32_t)(row * 64 +
                    (((ks * 2 + a_kg) ^ ((row >> 1) & 3)) * 16));
                ldmx4(Ahi[mt], sbase + byteoff);
                ldmx4(Alo[mt], sbase + 8192 + byteoff);
            }
            uint32_t Bhi[8][2];
            #pragma unroll
            for (int ntp = 0; ntp < 4; ntp++) {
                int n = nw + ntp * 16 + b_rlane;
                uint32_t byteoff = (uint32_t)(n * 64 +
                    (((ks * 2 + b_kg) ^ ((n >> 1) & 3)) * 16));
                uint32_t rh[4];
                ldmx4(rh, sbase + 16384 + byteoff);
                Bhi[ntp * 2][0] = rh[0]; Bhi[ntp * 2][1] = rh[1];
                Bhi[ntp * 2 + 1][0] = rh[2]; Bhi[ntp * 2 + 1][1] = rh[3];
            }
            #pragma unroll
            for (int mt = 0; mt < 2; mt++)
                #pragma unroll
                for (int nt = 0; nt < 8; nt++)
                    mma_f16(acc[mt][nt], Ahi[mt], Bhi[nt]);
            #pragma unroll
            for (int mt = 0; mt < 2; mt++)
                #pragma unroll
                for (int nt = 0; nt < 8; nt++)
                    mma_f16(acc[mt][nt], Alo[mt], Bhi[nt]);
        }
        __syncthreads();
    }

    // epilogue: convert to fp16 and store half2 per 2 cols
    #pragma unroll
    for (int mt = 0; mt < 2; mt++) {
        int row = bm + mw + mt * 16 + (lane >> 2);
        #pragma unroll
        for (int nt = 0; nt < 8; nt++) {
            int col = nw + nt * 8 + (lane & 3) * 2;
            __half2 p0 = __floats2half2_rn(acc[mt][nt][0], acc[mt][nt][1]);
            __half2 p1 = __floats2half2_rn(acc[mt][nt][2], acc[mt][nt][3]);
            if (row < N_NODES)
                *reinterpret_cast<__half2*>(&g_h1[(size_t)row * NH + col]) = p0;
            if (row + 8 < N_NODES)
                *reinterpret_cast<__half2*>(&g_h1[(size_t)(row + 8) * NH + col]) = p1;
        }
    }
}

// ---------------- agg1: paired-edge uint4 gather, fp32 accum ---------------
__global__ void agg1_kernel(const float* __restrict__ b1, int base, int count) {
    int t = blockIdx.x * blockDim.x + threadIdx.x;
    int w = (t >> 5);
    int lane = t & 31;
    if (w >= count) return;
    w += base;
    int beg = g_row_ptr[w], end = g_row_ptr[w + 1];

    const int half = lane >> 4;
    const int li   = lane & 15;

    unsigned long long a0 = 0ull, a1 = 0ull, a2 = 0ull, a3 = 0ull;
    for (int j = beg; j < end; j += 32) {
        int n = end - j; if (n > 32) n = 32;
        int2 ed = (j + lane < end) ? g_edge[j + lane] : make_int2(0, 0);
        #pragma unroll 8
        for (int i = 0; i < n; i += 2) {
            int e  = i + half;
            int   s = __shfl_sync(0xffffffffu, ed.x, e & 31);
            float f = __int_as_float(__shfl_sync(0xffffffffu, ed.y, e & 31));
            if (e >= n) { f = 0.f; s = 0; }
            uint4 v = __ldg(reinterpret_cast<const uint4*>(&g_h1[(size_t)s * NH]) + li);
            float2 f0 = __half22float2(*reinterpret_cast<__half2*>(&v.x));
            float2 f1 = __half22float2(*reinterpret_cast<__half2*>(&v.y));
            float2 f2 = __half22float2(*reinterpret_cast<__half2*>(&v.z));
            float2 f3 = __half22float2(*reinterpret_cast<__half2*>(&v.w));
            unsigned long long pf = pack2(f);
            fma2(a0, pf, packf2(f0.x, f0.y));
            fma2(a1, pf, packf2(f1.x, f1.y));
            fma2(a2, pf, packf2(f2.x, f2.y));
            fma2(a3, pf, packf2(f3.x, f3.y));
        }
    }
    unsigned long long c0 = __shfl_xor_sync(0xffffffffu, a0, 16);
    unsigned long long c1 = __shfl_xor_sync(0xffffffffu, a1, 16);
    unsigned long long c2 = __shfl_xor_sync(0xffffffffu, a2, 16);
    unsigned long long c3 = __shfl_xor_sync(0xffffffffu, a3, 16);
    float2 q0 = unpack2(a0), r0 = unpack2(c0);
    float2 q1 = unpack2(a1), r1 = unpack2(c1);
    float2 q2 = unpack2(a2), r2 = unpack2(c2);
    float2 q3 = unpack2(a3), r3 = unpack2(c3);

    if (half == 0) {
        float nd = g_nd[w];
        int fb = li * 8;
        float4 bA = __ldg(reinterpret_cast<const float4*>(b1 + fb));
        float4 bB = __ldg(reinterpret_cast<const float4*>(b1 + fb + 4));
        float4 oA, oB;
        oA.x = fmaxf((q0.x + r0.x) * nd + bA.x, 0.f);
        oA.y = fmaxf((q0.y + r0.y) * nd + bA.y, 0.f);
        oA.z = fmaxf((q1.x + r1.x) * nd + bA.z, 0.f);
        oA.w = fmaxf((q1.y + r1.y) * nd + bA.w, 0.f);
        oB.x = fmaxf((q2.x + r2.x) * nd + bB.x, 0.f);
        oB.y = fmaxf((q2.y + r2.y) * nd + bB.y, 0.f);
        oB.z = fmaxf((q3.x + r3.x) * nd + bB.z, 0.f);
        oB.w = fmaxf((q3.y + r3.y) * nd + bB.w, 0.f);
        *reinterpret_cast<float4*>(&g_x2[(size_t)w * NH + fb])     = oA;
        *reinterpret_cast<float4*>(&g_x2[(size_t)w * NH + fb + 4]) = oB;
    }
}

// ---------------- GEMM2 over [base, base+count): fp16 output ----------------
__global__ __launch_bounds__(256) void gemm2_kernel(const float* __restrict__ W2,
                                                    int base, int count) {
    __shared__ float W2s[NH * NC];
    __shared__ float xs[8][NH];

    int tid = threadIdx.x;
    for (int i = tid; i < NH * NC; i += 256) W2s[i] = W2[i];
    __syncthreads();

    const int n_tiles = (count + 7) / 8;
    for (int tile = blockIdx.x; tile < n_tiles; tile += gridDim.x) {
        int row0 = base + tile * 8;
        int lim  = base + count;
        #pragma unroll
        for (int i = 0; i < 4; i++) {
            int j = tid + i * 256;
            int r = j >> 7, k = j & 127;
            int row = row0 + r;
            xs[r][k] = (row < lim) ? g_x2[(size_t)row * NH + k] : 0.f;
        }
        __syncthreads();

        if (tid < 8 * (NC / 2)) {
            int r  = tid / (NC / 2);
            int cp = tid % (NC / 2);
            int row = row0 + r;
            if (row < lim) {
                unsigned long long acc = 0ull;
                const unsigned long long* wp =
                    reinterpret_cast<const unsigned long long*>(W2s) + cp;
                #pragma unroll 8
                for (int k = 0; k < NH; k++)
                    fma2(acc, pack2(xs[r][k]), wp[k * (NC / 2)]);
                float2 p = unpack2(acc);
                *reinterpret_cast<__half2*>(&g_h2h[(size_t)row * NC + cp * 2]) =
                    __floats2half2_rn(p.x, p.y);
            }
        }
        __syncthreads();
    }
}

// ---------------- agg2: fp16 gather; lanes 0-19 own 2 feats each -----------
__global__ void agg2_kernel(const float* __restrict__ b2, float* __restrict__ out) {
    int t = blockIdx.x * blockDim.x + threadIdx.x;
    int w = t >> 5, lane = t & 31;
    if (w >= N_NODES) return;
    int beg = g_row_ptr[w], end = g_row_ptr[w + 1];

    unsigned long long acc = 0ull;
    const bool act = lane < (NC / 2);
    for (int j = beg; j < end; j += 32) {
        int n = end - j; if (n > 32) n = 32;
        int2 ed = (j + lane < end) ? g_edge[j + lane] : make_int2(0, 0);
        #pragma unroll 8
        for (int i = 0; i < n; i++) {
            int   s = __shfl_sync(0xffffffffu, ed.x, i);
            float f = __int_as_float(__shfl_sync(0xffffffffu, ed.y, i));
            if (act) {
                uint32_t v = __ldg(reinterpret_cast<const uint32_t*>(
                    &g_h2h[(size_t)s * NC]) + lane);
                float2 fv = __half22float2(*reinterpret_cast<__half2*>(&v));
                fma2(acc, pack2(f), packf2(fv.x, fv.y));
            }
        }
    }
    if (act) {
        float nd = g_nd[w];
        float2 p = unpack2(acc);
        float2 bb = __ldg(reinterpret_cast<const float2*>(b2) + lane);
        *reinterpret_cast<float2*>(&out[(size_t)w * NC + lane * 2]) =
            make_float2(p.x * nd + bb.x, p.y * nd + bb.y);
    }
}

// ---------------- launch ----------------
extern "C" void kernel_launch(void* const* d_in, const int* in_sizes, int n_in,
                              void* d_out, int out_size) {
    const float* X   = (const float*)d_in[0];
    const float* W1  = (const float*)d_in[1];
    const float* b1  = (const float*)d_in[2];
    const float* W2  = (const float*)d_in[3];
    const float* b2  = (const float*)d_in[4];
    const int*   src = (const int*)  d_in[5];
    const int*   dst = (const int*)  d_in[6];
    float* out = (float*)d_out;

    static cudaStream_t s_side = nullptr;
    static cudaEvent_t  ev_fork = nullptr, ev_join = nullptr;
    static cudaEvent_t  ev_a = nullptr, ev_g2a = nullptr;
    if (s_side == nullptr) {
        cudaStreamCreateWithFlags(&s_side, cudaStreamNonBlocking);
        cudaEventCreateWithFlags(&ev_fork, cudaEventDisableTiming);
        cudaEventCreateWithFlags(&ev_join, cudaEventDisableTiming);
        cudaEventCreateWithFlags(&ev_a, cudaEventDisableTiming);
        cudaEventCreateWithFlags(&ev_g2a, cudaEventDisableTiming);
        cudaFuncSetAttribute(gemm1_mma_kernel,
                             cudaFuncAttributeMaxDynamicSharedMemorySize, G1M_SMEM);
    }

    // fork: side stream runs the graph-prep chain
    cudaEventRecord(ev_fork, 0);
    cudaStreamWaitEvent(s_side, ev_fork, 0);

    zero_kernel<<<256, 256, 0, s_side>>>();
    deg_kernel<<<(N_EDGES + 255) / 256, 256, 0, s_side>>>(src, dst);
    norm_kernel<<<(N_NODES + 255) / 256, 256, 0, s_side>>>();
    scan1_kernel<<<SCAN_B, 256, 0, s_side>>>();
    scan2_kernel<<<1, 256, 0, s_side>>>();
    scan3_kernel<<<SCAN_B, 256, 0, s_side>>>();
    fill_kernel<<<(N_EDGES + 255) / 256, 256, 0, s_side>>>(src, dst);

    // main stream: W1 fp16 convert + tensor-core GEMM1
    w1split_kernel<<<(IN_F * NH + 255) / 256, 256>>>(W1);
    gemm1_mma_kernel<<<(N_NODES + 127) / 128, 256, G1M_SMEM>>>(X);

    // join
    cudaEventRecord(ev_join, s_side);
    cudaStreamWaitEvent(0, ev_join, 0);

    // agg1 half A; gemm2(A) overlaps agg1 half B
    agg1_kernel<<<(N_HALF * 32 + 255) / 256, 256>>>(b1, 0, N_HALF);
    cudaEventRecord(ev_a, 0);
    cudaStreamWaitEvent(s_side, ev_a, 0);
    gemm2_kernel<<<1024, 256, 0, s_side>>>(W2, 0, N_HALF);

    agg1_kernel<<<((N_NODES - N_HALF) * 32 + 255) / 256, 256>>>(b1, N_HALF, N_NODES - N_HALF);
    gemm2_kernel<<<1024, 256>>>(W2, N_HALF, N_NODES - N_HALF);

    cudaEventRecord(ev_g2a, s_side);
    cudaStreamWaitEvent(0, ev_g2a, 0);

    agg2_kernel<<<(N_NODES * 32 + 255) / 256, 256>>>(b2, out);
}